// round 2
// baseline (speedup 1.0000x reference)
#include <cuda_runtime.h>
#include <cuda_bf16.h>

// ---------------------------------------------------------------------------
// LSTM_net: 2-layer LSTM (B=256,T=512,I=64,H=256) + MLP head.
//   K1 gemm_xg:  xg = A @ W_ihT + (b_ih+b_hh)   (tf32 mma.sync, fp32 accum)
//   K2 lstm_layer: persistent 128-CTA kernel; 8 batch-groups(32) x 16 slices.
//       W_hh slice resident in SMEM (tf32, paired-k layout). Per step:
//       reload h via __ldcg (L2, coherent), mma, gates, write h slice,
//       release-fenced phase barrier per group.
//   K3 head: tiny MLP.
// ---------------------------------------------------------------------------

#define BATCH  256
#define SEQ    512
#define INP    64
#define HID    256
#define GATE4  1024
#define NGROUP 8        // batch groups of 32
#define GROWS  32       // batch rows per group
#define NSLICE 16       // gate-column slices (16 j-cols x 4 gates = 64 rows of W_hh)

// Scratch (static device globals; allocation-free per harness rules)
__device__ float    g_xg  [(size_t)BATCH * SEQ * GATE4];
__device__ float    g_hseq[(size_t)BATCH * SEQ * HID];
__device__ float    g_hbuf[2 * BATCH * HID];          // ping-pong h (512 KB, L2-resident)
__device__ unsigned g_cnt  [NGROUP];
__device__ unsigned g_phase[NGROUP];

// ---------------- tf32 helpers ----------------
__device__ __forceinline__ unsigned f2tf(float f) {
    unsigned u;
    asm("cvt.rna.tf32.f32 %0, %1;" : "=r"(u) : "f"(f));
    return u;
}

__device__ __forceinline__ void mma_tf32(float d[4],
                                         unsigned a0, unsigned a1, unsigned a2, unsigned a3,
                                         unsigned b0, unsigned b1) {
    asm volatile(
        "mma.sync.aligned.m16n8k8.row.col.f32.tf32.tf32.f32 "
        "{%0,%1,%2,%3}, {%4,%5,%6,%7}, {%8,%9}, {%0,%1,%2,%3};"
        : "+f"(d[0]), "+f"(d[1]), "+f"(d[2]), "+f"(d[3])
        : "r"(a0), "r"(a1), "r"(a2), "r"(a3), "r"(b0), "r"(b1));
}

__device__ __forceinline__ float sigf(float x) {
    return 1.0f / (1.0f + __expf(-x));
}
__device__ __forceinline__ float tanh_fast(float x) {
    return 2.0f * sigf(2.0f * x) - 1.0f;   // saturation-safe, ~1e-6 abs err
}

// ---------------------------------------------------------------------------
// K1: C[M,1024] = A[M,K] @ W[1024,K]^T + (bih+bhh)   (tf32)
// CTA tile 64x64, K-step 32. 8 warps as 4(m) x 2(n); warp tile 16x32.
// ---------------------------------------------------------------------------
__global__ void __launch_bounds__(256) gemm_xg_kernel(
    const float* __restrict__ A, const float* __restrict__ W,
    const float* __restrict__ bih, const float* __restrict__ bhh,
    float* __restrict__ C, int K)
{
    __shared__ unsigned As[64][36];
    __shared__ unsigned Bs[64][36];

    const int tid  = threadIdx.x;
    const int lane = tid & 31;
    const int warp = tid >> 5;
    const int wm   = (warp & 3) * 16;
    const int wn   = (warp >> 2) * 32;
    const long m0  = (long)blockIdx.x * 64;
    const int  n0  = blockIdx.y * 64;

    float d[4][4] = {};

    for (int k0 = 0; k0 < K; k0 += 32) {
        #pragma unroll
        for (int i = 0; i < 2; i++) {
            int f   = tid + i * 256;
            int row = f >> 3;
            int c4  = (f & 7) * 4;
            float4 av = *reinterpret_cast<const float4*>(A + (m0 + row) * (long)K + k0 + c4);
            As[row][c4 + 0] = f2tf(av.x); As[row][c4 + 1] = f2tf(av.y);
            As[row][c4 + 2] = f2tf(av.z); As[row][c4 + 3] = f2tf(av.w);
            float4 bv = *reinterpret_cast<const float4*>(W + (long)(n0 + row) * K + k0 + c4);
            Bs[row][c4 + 0] = f2tf(bv.x); Bs[row][c4 + 1] = f2tf(bv.y);
            Bs[row][c4 + 2] = f2tf(bv.z); Bs[row][c4 + 3] = f2tf(bv.w);
        }
        __syncthreads();

        #pragma unroll
        for (int kf = 0; kf < 4; kf++) {
            const int kb = kf * 8;
            const int gp = lane >> 2;
            const int tg = lane & 3;
            unsigned a0 = As[wm + gp    ][kb + tg    ];
            unsigned a1 = As[wm + gp + 8][kb + tg    ];
            unsigned a2 = As[wm + gp    ][kb + tg + 4];
            unsigned a3 = As[wm + gp + 8][kb + tg + 4];
            #pragma unroll
            for (int nf = 0; nf < 4; nf++) {
                unsigned b0 = Bs[wn + nf * 8 + gp][kb + tg    ];
                unsigned b1 = Bs[wn + nf * 8 + gp][kb + tg + 4];
                mma_tf32(d[nf], a0, a1, a2, a3, b0, b1);
            }
        }
        __syncthreads();
    }

    const int r = wm + (lane >> 2);
    #pragma unroll
    for (int nf = 0; nf < 4; nf++) {
        int c = n0 + wn + nf * 8 + 2 * (lane & 3);
        float bi0 = bih[c] + bhh[c];
        float bi1 = bih[c + 1] + bhh[c + 1];
        C[(m0 + r    ) * GATE4 + c    ] = d[nf][0] + bi0;
        C[(m0 + r    ) * GATE4 + c + 1] = d[nf][1] + bi1;
        C[(m0 + r + 8) * GATE4 + c    ] = d[nf][2] + bi0;
        C[(m0 + r + 8) * GATE4 + c + 1] = d[nf][3] + bi1;
    }
}

// ---------------------------------------------------------------------------
// K2: persistent LSTM layer. 128 CTAs = 8 batch-groups x 16 slices.
// Paired-k SMEM layout: within each 8-col k-block, column order
// [0,4,1,5,2,6,3,7] so fragment pair (tg, tg+4) is one contiguous LDS.64.
// ---------------------------------------------------------------------------
#define WSTR 264   // words/row; 264 % 32 == 8 -> conflict-free paired LDS.64
#define GSTR 68
#define SMEM_REC ((64 * WSTR + GROWS * WSTR + GROWS * GSTR + GROWS * 16) * 4)

__device__ __forceinline__ void group_barrier(int group, unsigned target) {
    __threadfence();          // release: every thread orders its h stores
    __syncthreads();
    if (threadIdx.x == 0) {
        unsigned old = atomicAdd(&g_cnt[group], 1u);
        if (old == (NSLICE - 1)) {
            *((volatile unsigned*)&g_cnt[group]) = 0u;
            __threadfence();
            atomicAdd(&g_phase[group], 1u);
        } else {
            while ((int)(*((volatile unsigned*)&g_phase[group]) - target) < 0) {
                unsigned ns = 64;
                asm volatile("nanosleep.u32 %0;" :: "r"(ns));
            }
        }
    }
    __syncthreads();
}

__global__ void __launch_bounds__(256, 1) lstm_layer_kernel(
    const float* __restrict__ xg, const float* __restrict__ Whh,
    float* __restrict__ hseq, float* __restrict__ hbuf)
{
    extern __shared__ unsigned smem[];
    unsigned* Ws = smem;                                  // [64][WSTR]  resident weights
    unsigned* Hs = smem + 64 * WSTR;                      // [32][WSTR]  h_prev (tf32)
    float*    Gs = (float*)(smem + (64 + GROWS) * WSTR);  // [32][GSTR]  gate pre-acts
    float*    Cs = Gs + GROWS * GSTR;                     // [512]       cell state

    const int tid   = threadIdx.x;
    const int lane  = tid & 31;
    const int warp  = tid >> 5;
    const int group = blockIdx.x >> 4;
    const int slice = blockIdx.x & 15;
    const int b0    = group * GROWS;
    const int j0    = slice * 16;
    const int wm    = (warp & 1) * 16;       // 2 m-warps x 4 n-warps
    const int wn    = (warp >> 1) * 16;

    // paired-k position for this thread's column (= tid, 0..255)
    const int pcol = ((tid >> 3) << 3) + ((tid & 3) << 1) + ((tid >> 2) & 1);

    __shared__ unsigned s_ph0;
    if (tid == 0) s_ph0 = *((volatile unsigned*)&g_phase[group]);

    // resident weight slice: local row rl = gate*16+jj  <-  W_hh[gate*256+j0+jj, :]
    for (int e = tid; e < 64 * 256; e += 256) {
        int rl = e >> 8;                           // k == tid for every e
        int gr = (rl >> 4) * 256 + j0 + (rl & 15);
        Ws[rl * WSTR + pcol] = f2tf(Whh[gr * 256 + tid]);
    }
    // zero cell state + our slice of hbuf buffer 0
    for (int e = tid; e < GROWS * 16; e += 256) {
        Cs[e] = 0.0f;
        int bl = e >> 4, j = e & 15;
        hbuf[(b0 + bl) * HID + j0 + j] = 0.0f;
    }
    __syncthreads();                     // publishes s_ph0 too
    const unsigned ph0 = s_ph0;
    group_barrier(group, ph0 + 1);       // h(0) fully zeroed + visible at L2

    for (int t = 0; t < SEQ; t++) {
        const float* hsrc = hbuf + (t & 1) * (BATCH * HID);
        float*       hdst = hbuf + ((t + 1) & 1) * (BATCH * HID);

        // reload h_prev for our 32 batch rows; MUST bypass L1 (other SMs wrote it)
        #pragma unroll 8
        for (int i = 0; i < GROWS; i++)
            Hs[i * WSTR + pcol] = f2tf(__ldcg(&hsrc[(b0 + i) * HID + tid]));
        __syncthreads();

        float d[2][4] = {};
        const int gp = lane >> 2;
        const int tg = lane & 3;
        #pragma unroll 8
        for (int kf = 0; kf < 32; kf++) {
            const int kb = kf * 8;
            // A pair loads: (col tg, col tg+4) adjacent in paired layout
            uint2 va = *reinterpret_cast<const uint2*>(&Hs[(wm + gp    ) * WSTR + kb + 2 * tg]);
            uint2 vb = *reinterpret_cast<const uint2*>(&Hs[(wm + gp + 8) * WSTR + kb + 2 * tg]);
            #pragma unroll
            for (int nf = 0; nf < 2; nf++) {
                uint2 vw = *reinterpret_cast<const uint2*>(&Ws[(wn + nf * 8 + gp) * WSTR + kb + 2 * tg]);
                mma_tf32(d[nf], va.x, vb.x, va.y, vb.y, vw.x, vw.y);
            }
        }

        // stage gate pre-activations to SMEM (cross-warp reshuffle)
        {
            const int r = wm + gp;
            #pragma unroll
            for (int nf = 0; nf < 2; nf++) {
                int c = wn + nf * 8 + 2 * tg;
                Gs[ r      * GSTR + c    ] = d[nf][0];
                Gs[ r      * GSTR + c + 1] = d[nf][1];
                Gs[(r + 8) * GSTR + c    ] = d[nf][2];
                Gs[(r + 8) * GSTR + c + 1] = d[nf][3];
            }
        }
        __syncthreads();

        // gate nonlinearity + state update: each thread owns 2 (b,j) cells
        #pragma unroll
        for (int rr = 0; rr < 2; rr++) {
            int bl = rr * 16 + (tid >> 4);
            int j  = tid & 15;
            long xbase = ((long)(b0 + bl) * SEQ + t) * GATE4 + j0 + j;
            float gi = Gs[bl * GSTR +      j] + __ldg(&xg[xbase      ]);
            float gf = Gs[bl * GSTR + 16 + j] + __ldg(&xg[xbase + 256]);
            float gg = Gs[bl * GSTR + 32 + j] + __ldg(&xg[xbase + 512]);
            float go = Gs[bl * GSTR + 48 + j] + __ldg(&xg[xbase + 768]);
            float si = sigf(gi), sf = sigf(gf), so = sigf(go);
            float cv = sf * Cs[bl * 16 + j] + si * tanh_fast(gg);
            Cs[bl * 16 + j] = cv;
            float hn = so * tanh_fast(cv);
            hdst[(b0 + bl) * HID + j0 + j] = hn;
            hseq[((long)(b0 + bl) * SEQ + t) * HID + j0 + j] = hn;
        }
        group_barrier(group, ph0 + 2 + t);
    }
}

// ---------------------------------------------------------------------------
// K3: head. out[b, :] = tanh(h_last @ W1^T + b1) @ W2^T + b2
// ---------------------------------------------------------------------------
__global__ void __launch_bounds__(128) head_kernel(
    const float* __restrict__ hseq,
    const float* __restrict__ W1, const float* __restrict__ b1,
    const float* __restrict__ W2, const float* __restrict__ b2,
    float* __restrict__ out)
{
    __shared__ float hl[256];
    __shared__ float z[128];
    const int b = blockIdx.x, tid = threadIdx.x;

    for (int i = tid; i < 256; i += 128)
        hl[i] = hseq[((long)b * SEQ + (SEQ - 1)) * HID + i];
    __syncthreads();

    {
        float acc = b1[tid];
        const float* w = W1 + tid * 256;
        #pragma unroll 8
        for (int h = 0; h < 256; h++) acc += hl[h] * w[h];
        z[tid] = tanhf(acc);
    }
    __syncthreads();

    if (tid < 96) {
        float acc = b2[tid];
        const float* w = W2 + tid * 128;
        #pragma unroll 8
        for (int l = 0; l < 128; l++) acc += z[l] * w[l];
        out[b * 96 + tid] = acc;
    }
}

// ---------------------------------------------------------------------------
extern "C" void kernel_launch(void* const* d_in, const int* in_sizes, int n_in,
                              void* d_out, int out_size)
{
    const float* x    = (const float*)d_in[0];
    const float* Wih0 = (const float*)d_in[1];
    const float* Whh0 = (const float*)d_in[2];
    const float* bih0 = (const float*)d_in[3];
    const float* bhh0 = (const float*)d_in[4];
    const float* Wih1 = (const float*)d_in[5];
    const float* Whh1 = (const float*)d_in[6];
    const float* bih1 = (const float*)d_in[7];
    const float* bhh1 = (const float*)d_in[8];
    const float* W1   = (const float*)d_in[9];
    const float* b1   = (const float*)d_in[10];
    const float* W2   = (const float*)d_in[11];
    const float* b2   = (const float*)d_in[12];
    float* out = (float*)d_out;

    float *xg, *hseq, *hbuf;
    cudaGetSymbolAddress((void**)&xg,   g_xg);
    cudaGetSymbolAddress((void**)&hseq, g_hseq);
    cudaGetSymbolAddress((void**)&hbuf, g_hbuf);

    cudaFuncSetAttribute((const void*)lstm_layer_kernel,
                         cudaFuncAttributeMaxDynamicSharedMemorySize, SMEM_REC);

    dim3 gg((BATCH * SEQ) / 64, GATE4 / 64);

    // layer 0
    gemm_xg_kernel<<<gg, 256>>>(x, Wih0, bih0, bhh0, xg, INP);
    lstm_layer_kernel<<<NGROUP * NSLICE, 256, SMEM_REC>>>(xg, Whh0, hseq, hbuf);
    // layer 1
    gemm_xg_kernel<<<gg, 256>>>(hseq, Wih1, bih1, bhh1, xg, HID);
    lstm_layer_kernel<<<NGROUP * NSLICE, 256, SMEM_REC>>>(xg, Whh1, hseq, hbuf);
    // head
    head_kernel<<<BATCH, 128>>>(hseq, W1, b1, W2, b2, out);
}

// round 4
// speedup vs baseline: 1.3748x; 1.3748x over previous
#include <cuda_runtime.h>
#include <cuda_bf16.h>

// ---------------------------------------------------------------------------
// LSTM_net: 2-layer LSTM (B=256,T=512,I=64,H=256) + MLP head.
//   K1 gemm_xg:  xg = A @ W_ihT + (b_ih+b_hh)   (tf32 mma.sync, fp32 accum)
//   K2 lstm_layer: persistent 128-CTA kernel; 8 batch-groups(32) x 16 slices.
//       W_hh slice resident in SMEM (tf32, paired-k layout). Per step:
//       prefetch xg, WAIT (acquire-spin on monotonic counter), reload h via
//       __ldcg, mma, gates, write h slice, ARRIVE (release red.add).
//       Exactly ONE arrival per CTA per step.
//   K3 head: tiny MLP.
// ---------------------------------------------------------------------------

#define BATCH  256
#define SEQ    512
#define INP    64
#define HID    256
#define GATE4  1024
#define NGROUP 8        // batch groups of 32
#define GROWS  32       // batch rows per group
#define NSLICE 16       // gate-column slices (16 j-cols x 4 gates = 64 rows of W_hh)

// Scratch (static device globals; allocation-free per harness rules)
__device__ float    g_xg  [(size_t)BATCH * SEQ * GATE4];
__device__ float    g_hseq[(size_t)BATCH * SEQ * HID];
__device__ float    g_hbuf[2 * BATCH * HID];          // ping-pong h (512 KB, L2-resident)
__device__ unsigned g_cnt [NGROUP];                   // monotonic arrival counters

// ---------------- tf32 helpers ----------------
__device__ __forceinline__ unsigned f2tf(float f) {
    unsigned u;
    asm("cvt.rna.tf32.f32 %0, %1;" : "=r"(u) : "f"(f));
    return u;
}

__device__ __forceinline__ void mma_tf32(float d[4],
                                         unsigned a0, unsigned a1, unsigned a2, unsigned a3,
                                         unsigned b0, unsigned b1) {
    asm volatile(
        "mma.sync.aligned.m16n8k8.row.col.f32.tf32.tf32.f32 "
        "{%0,%1,%2,%3}, {%4,%5,%6,%7}, {%8,%9}, {%0,%1,%2,%3};"
        : "+f"(d[0]), "+f"(d[1]), "+f"(d[2]), "+f"(d[3])
        : "r"(a0), "r"(a1), "r"(a2), "r"(a3), "r"(b0), "r"(b1));
}

__device__ __forceinline__ float sigf(float x) {
    return 1.0f / (1.0f + __expf(-x));
}
__device__ __forceinline__ float tanh_fast(float x) {
    return 2.0f * sigf(2.0f * x) - 1.0f;   // saturation-safe, ~1e-6 abs err
}

// ---------------- release/acquire sync primitives ----------------
__device__ __forceinline__ void red_add_release(unsigned* p) {
    asm volatile("red.global.add.release.gpu.u32 [%0], %1;"
                 :: "l"(p), "r"(1u) : "memory");
}
__device__ __forceinline__ unsigned ld_acquire(const unsigned* p) {
    unsigned v;
    asm volatile("ld.global.acquire.gpu.u32 %0, [%1];"
                 : "=r"(v) : "l"(p) : "memory");
    return v;
}

// ---------------------------------------------------------------------------
// K0: zero the group counters (run before each lstm launch)
// ---------------------------------------------------------------------------
__global__ void reset_sync_kernel() {
    if (threadIdx.x < NGROUP) g_cnt[threadIdx.x] = 0u;
}

// ---------------------------------------------------------------------------
// K1: C[M,1024] = A[M,K] @ W[1024,K]^T + (bih+bhh)   (tf32)
// CTA tile 64x64, K-step 32. Grid: x = n-blocks (fast) so n-blocks sharing
// an A tile run in the same wave -> A served from L2, not DRAM.
// ---------------------------------------------------------------------------
__global__ void __launch_bounds__(256) gemm_xg_kernel(
    const float* __restrict__ A, const float* __restrict__ W,
    const float* __restrict__ bih, const float* __restrict__ bhh,
    float* __restrict__ C, int K)
{
    __shared__ unsigned As[64][36];
    __shared__ unsigned Bs[64][36];

    const int tid  = threadIdx.x;
    const int lane = tid & 31;
    const int warp = tid >> 5;
    const int wm   = (warp & 3) * 16;
    const int wn   = (warp >> 2) * 32;
    const int  n0  = blockIdx.x * 64;             // n fast-varying
    const long m0  = (long)blockIdx.y * 64;

    float d[4][4] = {};

    for (int k0 = 0; k0 < K; k0 += 32) {
        #pragma unroll
        for (int i = 0; i < 2; i++) {
            int f   = tid + i * 256;
            int row = f >> 3;
            int c4  = (f & 7) * 4;
            float4 av = *reinterpret_cast<const float4*>(A + (m0 + row) * (long)K + k0 + c4);
            As[row][c4 + 0] = f2tf(av.x); As[row][c4 + 1] = f2tf(av.y);
            As[row][c4 + 2] = f2tf(av.z); As[row][c4 + 3] = f2tf(av.w);
            float4 bv = *reinterpret_cast<const float4*>(W + (long)(n0 + row) * K + k0 + c4);
            Bs[row][c4 + 0] = f2tf(bv.x); Bs[row][c4 + 1] = f2tf(bv.y);
            Bs[row][c4 + 2] = f2tf(bv.z); Bs[row][c4 + 3] = f2tf(bv.w);
        }
        __syncthreads();

        #pragma unroll
        for (int kf = 0; kf < 4; kf++) {
            const int kb = kf * 8;
            const int gp = lane >> 2;
            const int tg = lane & 3;
            unsigned a0 = As[wm + gp    ][kb + tg    ];
            unsigned a1 = As[wm + gp + 8][kb + tg    ];
            unsigned a2 = As[wm + gp    ][kb + tg + 4];
            unsigned a3 = As[wm + gp + 8][kb + tg + 4];
            #pragma unroll
            for (int nf = 0; nf < 4; nf++) {
                unsigned b0 = Bs[wn + nf * 8 + gp][kb + tg    ];
                unsigned b1 = Bs[wn + nf * 8 + gp][kb + tg + 4];
                mma_tf32(d[nf], a0, a1, a2, a3, b0, b1);
            }
        }
        __syncthreads();
    }

    const int r = wm + (lane >> 2);
    #pragma unroll
    for (int nf = 0; nf < 4; nf++) {
        int c = n0 + wn + nf * 8 + 2 * (lane & 3);
        float bi0 = bih[c] + bhh[c];
        float bi1 = bih[c + 1] + bhh[c + 1];
        C[(m0 + r    ) * GATE4 + c    ] = d[nf][0] + bi0;
        C[(m0 + r    ) * GATE4 + c + 1] = d[nf][1] + bi1;
        C[(m0 + r + 8) * GATE4 + c    ] = d[nf][2] + bi0;
        C[(m0 + r + 8) * GATE4 + c + 1] = d[nf][3] + bi1;
    }
}

// ---------------------------------------------------------------------------
// K2: persistent LSTM layer. 128 CTAs = 8 batch-groups x 16 slices.
// Paired-k SMEM layout: within each 8-col k-block, column order
// [0,4,1,5,2,6,3,7] so fragment pair (tg, tg+4) is one contiguous LDS.64.
// ---------------------------------------------------------------------------
#define WSTR 264   // words/row; 264 % 32 == 8 -> conflict-free paired LDS.64
#define GSTR 68
#define SMEM_REC ((64 * WSTR + GROWS * WSTR + GROWS * GSTR + GROWS * 16) * 4)

// ARRIVE: bar.sync orders all block stores before thread0's release-add.
__device__ __forceinline__ void group_arrive(int group) {
    __syncthreads();
    if (threadIdx.x == 0) red_add_release(&g_cnt[group]);
}
// WAIT: thread0 acquire-spins to target, bar.sync broadcasts visibility.
__device__ __forceinline__ void group_wait(int group, unsigned target) {
    if (threadIdx.x == 0) {
        while ((int)(ld_acquire(&g_cnt[group]) - target) < 0) { }
    }
    __syncthreads();
}

__global__ void __launch_bounds__(256, 1) lstm_layer_kernel(
    const float* __restrict__ xg, const float* __restrict__ Whh,
    float* __restrict__ hseq, float* __restrict__ hbuf, int store_all)
{
    extern __shared__ unsigned smem[];
    unsigned* Ws = smem;                                  // [64][WSTR]  resident weights
    unsigned* Hs = smem + 64 * WSTR;                      // [32][WSTR]  h_prev (tf32)
    float*    Gs = (float*)(smem + (64 + GROWS) * WSTR);  // [32][GSTR]  gate pre-acts
    float*    Cs = Gs + GROWS * GSTR;                     // [512]       cell state

    const int tid   = threadIdx.x;
    const int lane  = tid & 31;
    const int warp  = tid >> 5;
    const int group = blockIdx.x >> 4;
    const int slice = blockIdx.x & 15;
    const int b0    = group * GROWS;
    const int j0    = slice * 16;
    const int wm    = (warp & 1) * 16;       // 2 m-warps x 4 n-warps
    const int wn    = (warp >> 1) * 16;

    // paired-k position for this thread's column (= tid, 0..255)
    const int pcol = ((tid >> 3) << 3) + ((tid & 3) << 1) + ((tid >> 2) & 1);

    // resident weight slice: local row rl = gate*16+jj  <-  W_hh[gate*256+j0+jj, :]
    for (int e = tid; e < 64 * 256; e += 256) {
        int rl = e >> 8;                           // k == tid for every e
        int gr = (rl >> 4) * 256 + j0 + (rl & 15);
        Ws[rl * WSTR + pcol] = f2tf(Whh[gr * 256 + tid]);
    }
    // zero cell state + our slice of hbuf buffer 0
    for (int e = tid; e < GROWS * 16; e += 256) {
        Cs[e] = 0.0f;
        int bl = e >> 4, j = e & 15;
        hbuf[(b0 + bl) * HID + j0 + j] = 0.0f;
    }
    group_arrive(group);        // arrival #1: h(0) zeroed + published

    // epilogue cell indices for this thread
    const int ebl = tid >> 4;            // 0..15
    const int ej  = tid & 15;

    for (int t = 0; t < SEQ; t++) {
        const float* hsrc = hbuf + (t & 1) * (BATCH * HID);
        float*       hdst = hbuf + ((t + 1) & 1) * (BATCH * HID);

        // prefetch xg for this step (independent of the barrier) - hides DRAM
        float xr[8];
        #pragma unroll
        for (int rr = 0; rr < 2; rr++) {
            int bl = rr * 16 + ebl;
            long xbase = ((long)(b0 + bl) * SEQ + t) * GATE4 + j0 + ej;
            xr[rr * 4 + 0] = __ldg(&xg[xbase      ]);
            xr[rr * 4 + 1] = __ldg(&xg[xbase + 256]);
            xr[rr * 4 + 2] = __ldg(&xg[xbase + 512]);
            xr[rr * 4 + 3] = __ldg(&xg[xbase + 768]);
        }

        // wait: all 16 slices of this group have made t+1 arrivals
        group_wait(group, (unsigned)(t + 1) * NSLICE);

        // reload h_prev for our 32 batch rows; MUST bypass L1 (other SMs wrote it)
        #pragma unroll
        for (int i = 0; i < GROWS; i++)
            Hs[i * WSTR + pcol] = f2tf(__ldcg(&hsrc[(b0 + i) * HID + tid]));
        __syncthreads();

        float d[2][4] = {};
        const int gp = lane >> 2;
        const int tg = lane & 3;
        #pragma unroll 8
        for (int kf = 0; kf < 32; kf++) {
            const int kb = kf * 8;
            uint2 va = *reinterpret_cast<const uint2*>(&Hs[(wm + gp    ) * WSTR + kb + 2 * tg]);
            uint2 vb = *reinterpret_cast<const uint2*>(&Hs[(wm + gp + 8) * WSTR + kb + 2 * tg]);
            #pragma unroll
            for (int nf = 0; nf < 2; nf++) {
                uint2 vw = *reinterpret_cast<const uint2*>(&Ws[(wn + nf * 8 + gp) * WSTR + kb + 2 * tg]);
                mma_tf32(d[nf], va.x, vb.x, va.y, vb.y, vw.x, vw.y);
            }
        }

        // stage gate pre-activations to SMEM (cross-warp reshuffle)
        {
            const int r = wm + gp;
            #pragma unroll
            for (int nf = 0; nf < 2; nf++) {
                int c = wn + nf * 8 + 2 * tg;
                Gs[ r      * GSTR + c    ] = d[nf][0];
                Gs[ r      * GSTR + c + 1] = d[nf][1];
                Gs[(r + 8) * GSTR + c    ] = d[nf][2];
                Gs[(r + 8) * GSTR + c + 1] = d[nf][3];
            }
        }
        __syncthreads();

        // gate nonlinearity + state update: each thread owns 2 (b,j) cells
        #pragma unroll
        for (int rr = 0; rr < 2; rr++) {
            int bl = rr * 16 + ebl;
            float gi = Gs[bl * GSTR +      ej] + xr[rr * 4 + 0];
            float gf = Gs[bl * GSTR + 16 + ej] + xr[rr * 4 + 1];
            float gg = Gs[bl * GSTR + 32 + ej] + xr[rr * 4 + 2];
            float go = Gs[bl * GSTR + 48 + ej] + xr[rr * 4 + 3];
            float si = sigf(gi), sf = sigf(gf), so = sigf(go);
            float cv = sf * Cs[bl * 16 + ej] + si * tanh_fast(gg);
            Cs[bl * 16 + ej] = cv;
            float hn = so * tanh_fast(cv);
            hdst[(b0 + bl) * HID + j0 + ej] = hn;
            if (store_all || t == SEQ - 1)
                hseq[((long)(b0 + bl) * SEQ + t) * HID + j0 + ej] = hn;
        }
        group_arrive(group);     // exactly one arrival per CTA per step
    }
}

// ---------------------------------------------------------------------------
// K3: head. out[b, :] = tanh(h_last @ W1^T + b1) @ W2^T + b2
// ---------------------------------------------------------------------------
__global__ void __launch_bounds__(128) head_kernel(
    const float* __restrict__ hseq,
    const float* __restrict__ W1, const float* __restrict__ b1,
    const float* __restrict__ W2, const float* __restrict__ b2,
    float* __restrict__ out)
{
    __shared__ float hl[256];
    __shared__ float z[128];
    const int b = blockIdx.x, tid = threadIdx.x;

    for (int i = tid; i < 256; i += 128)
        hl[i] = hseq[((long)b * SEQ + (SEQ - 1)) * HID + i];
    __syncthreads();

    {
        float acc = b1[tid];
        const float* w = W1 + tid * 256;
        #pragma unroll 8
        for (int h = 0; h < 256; h++) acc += hl[h] * w[h];
        z[tid] = tanhf(acc);
    }
    __syncthreads();

    if (tid < 96) {
        float acc = b2[tid];
        const float* w = W2 + tid * 128;
        #pragma unroll 8
        for (int l = 0; l < 128; l++) acc += z[l] * w[l];
        out[b * 96 + tid] = acc;
    }
}

// ---------------------------------------------------------------------------
extern "C" void kernel_launch(void* const* d_in, const int* in_sizes, int n_in,
                              void* d_out, int out_size)
{
    const float* x    = (const float*)d_in[0];
    const float* Wih0 = (const float*)d_in[1];
    const float* Whh0 = (const float*)d_in[2];
    const float* bih0 = (const float*)d_in[3];
    const float* bhh0 = (const float*)d_in[4];
    const float* Wih1 = (const float*)d_in[5];
    const float* Whh1 = (const float*)d_in[6];
    const float* bih1 = (const float*)d_in[7];
    const float* bhh1 = (const float*)d_in[8];
    const float* W1   = (const float*)d_in[9];
    const float* b1   = (const float*)d_in[10];
    const float* W2   = (const float*)d_in[11];
    const float* b2   = (const float*)d_in[12];
    float* out = (float*)d_out;

    float *xg, *hseq, *hbuf;
    cudaGetSymbolAddress((void**)&xg,   g_xg);
    cudaGetSymbolAddress((void**)&hseq, g_hseq);
    cudaGetSymbolAddress((void**)&hbuf, g_hbuf);

    cudaFuncSetAttribute((const void*)lstm_layer_kernel,
                         cudaFuncAttributeMaxDynamicSharedMemorySize, SMEM_REC);

    dim3 gg(GATE4 / 64, (BATCH * SEQ) / 64);   // n fast-varying: A reuse in L2

    // layer 0
    gemm_xg_kernel<<<gg, 256>>>(x, Wih0, bih0, bhh0, xg, INP);
    reset_sync_kernel<<<1, 32>>>();
    lstm_layer_kernel<<<NGROUP * NSLICE, 256, SMEM_REC>>>(xg, Whh0, hseq, hbuf, 1);
    // layer 1
    gemm_xg_kernel<<<gg, 256>>>(hseq, Wih1, bih1, bhh1, xg, HID);
    reset_sync_kernel<<<1, 32>>>();
    lstm_layer_kernel<<<NGROUP * NSLICE, 256, SMEM_REC>>>(xg, Whh1, hseq, hbuf, 0);
    // head
    head_kernel<<<BATCH, 128>>>(hseq, W1, b1, W2, b2, out);
}